// round 2
// baseline (speedup 1.0000x reference)
#include <cuda_runtime.h>

typedef unsigned long long u64;

constexpr int D = 128;   // feature dim
constexpr int K = 32;    // neighbors per node
constexpr int H = 32;    // attention hidden
constexpr int O = 128;   // output dim per branch
constexpr int WARPS = 8;            // nodes per block (1 warp per node)
constexpr int NTHREADS = WARPS * 32;
constexpr int RB = 4;               // neighbor rows per batch
constexpr int NBATCH = K / RB;      // 8

__device__ __forceinline__ u64 pack2(float lo, float hi) {
    u64 r; asm("mov.b64 %0, {%1, %2};" : "=l"(r) : "f"(lo), "f"(hi)); return r;
}
__device__ __forceinline__ float2 unpack2(u64 v) {
    float2 f; asm("mov.b64 {%0, %1}, %2;" : "=f"(f.x), "=f"(f.y) : "l"(v)); return f;
}
// d = a*b + c (packed 2 x f32)
__device__ __forceinline__ u64 ffma2(u64 a, u64 b, u64 c) {
    u64 d; asm("fma.rn.f32x2 %0, %1, %2, %3;" : "=l"(d) : "l"(a), "l"(b), "l"(c)); return d;
}
__device__ __forceinline__ float warp_sum(float v) {
    #pragma unroll
    for (int o = 16; o > 0; o >>= 1) v += __shfl_xor_sync(0xffffffffu, v, o);
    return v;
}

__global__ __launch_bounds__(NTHREADS)
void attn_agg_kernel(const float* __restrict__ node_feats,
                     const float* __restrict__ neib_feats,
                     const float* __restrict__ W_att1,   // [D,H] row-major
                     const float* __restrict__ W_att2,   // [H,H] row-major
                     const float* __restrict__ W_node,   // [D,O] row-major
                     const float* __restrict__ W_neib,   // [D,O] row-major
                     float* __restrict__ out,            // [N, 2*O]
                     int n)
{
    // sW1[p*32+h] = {W_att1[2p][h], W_att1[2p+1][h]}  (d-pair packed for f32x2)
    __shared__ u64    sW1[64 * 32];        // 16 KB
    __shared__ float  sW2[32 * 33];        // padded stride 33 (conflict-free both ways)
    __shared__ float4 sRow[WARPS][RB * 32];// 16 KB: per-warp neighbor batch
    __shared__ float4 sX[WARPS][32];       // 4 KB: per-warp node row
    __shared__ float  sT[WARPS][32];       // per-warp H-vector scratch

    const int tid  = threadIdx.x;
    const int lane = tid & 31;
    const int warp = tid >> 5;

    for (int i = tid; i < 64 * 32; i += NTHREADS) {
        int p = i >> 5, h = i & 31;
        sW1[i] = pack2(W_att1[(2 * p) * H + h], W_att1[(2 * p + 1) * H + h]);
    }
    for (int i = tid; i < 32 * 32; i += NTHREADS) {
        sW2[(i >> 5) * 33 + (i & 31)] = W_att2[i];
    }
    __syncthreads();

    const int node = blockIdx.x * WARPS + warp;
    if (node >= n) return;

    const float* nrow = node_feats + (size_t)node * D;
    const float* nb   = neib_feats + (size_t)node * (K * D);

    // ---- stage node row ----
    sX[warp][lane] = reinterpret_cast<const float4*>(nrow)[lane];
    __syncwarp();
    const u64* x64 = reinterpret_cast<const u64*>(&sX[warp][0]);

    // ---- t_node[lane] = tanh(node_row . W1[:,lane]) ----
    u64 a01 = 0ull, a23 = 0ull;
    #pragma unroll
    for (int d0 = 0; d0 < 32; ++d0) {
        u64 w01 = sW1[(2 * d0) * 32 + lane];
        u64 w23 = sW1[(2 * d0 + 1) * 32 + lane];
        a01 = ffma2(x64[2 * d0],     w01, a01);
        a23 = ffma2(x64[2 * d0 + 1], w23, a23);
    }
    {
        float2 qa = unpack2(a01), qb = unpack2(a23);
        sT[warp][lane] = tanhf(qa.x + qa.y + qb.x + qb.y);
    }
    __syncwarp();

    // ---- node_att[lane] = sum_h' t_node[h'] * W2[h'][lane] ----
    float na = 0.f;
    #pragma unroll
    for (int h = 0; h < 32; ++h) na += sT[warp][h] * sW2[h * 33 + lane];
    __syncwarp();
    sT[warp][lane] = na;
    __syncwarp();

    // ---- u[lane] = sum_h W2[lane][h] * node_att[h]  (folds W2 out of the K loop) ----
    float u = 0.f;
    #pragma unroll
    for (int h = 0; h < 32; ++h) u += sW2[lane * 33 + h] * sT[warp][h];

    // ---- neighbor loop: scores + online softmax + weighted aggregation, one pass ----
    float m = -1e30f, Z = 0.f;
    float4 agg = make_float4(0.f, 0.f, 0.f, 0.f);
    const u64* r64 = reinterpret_cast<const u64*>(&sRow[warp][0]);

    // prefetch batch 0
    float4 pre[RB];
    #pragma unroll
    for (int j = 0; j < RB; ++j)
        pre[j] = reinterpret_cast<const float4*>(nb + (size_t)j * D)[lane];

    #pragma unroll 1
    for (int b = 0; b < NBATCH; ++b) {
        #pragma unroll
        for (int j = 0; j < RB; ++j) sRow[warp][j * 32 + lane] = pre[j];
        __syncwarp();

        if (b + 1 < NBATCH) {
            #pragma unroll
            for (int j = 0; j < RB; ++j)
                pre[j] = reinterpret_cast<const float4*>(
                             nb + (size_t)((b + 1) * RB + j) * D)[lane];
        }

        u64 acc01[RB], acc23[RB];
        #pragma unroll
        for (int j = 0; j < RB; ++j) { acc01[j] = 0ull; acc23[j] = 0ull; }

        #pragma unroll
        for (int d0 = 0; d0 < 32; ++d0) {
            u64 w01 = sW1[(2 * d0) * 32 + lane];
            u64 w23 = sW1[(2 * d0 + 1) * 32 + lane];
            #pragma unroll
            for (int j = 0; j < RB; ++j) {
                acc01[j] = ffma2(r64[j * 64 + 2 * d0],     w01, acc01[j]);
                acc23[j] = ffma2(r64[j * 64 + 2 * d0 + 1], w23, acc23[j]);
            }
        }

        float s[RB];
        #pragma unroll
        for (int j = 0; j < RB; ++j) {
            float2 q0 = unpack2(acc01[j]), q1 = unpack2(acc23[j]);
            float t = tanhf(q0.x + q0.y + q1.x + q1.y);
            s[j] = warp_sum(t * u);      // score for neighbor b*RB+j (all lanes)
        }

        float bm = fmaxf(fmaxf(s[0], s[1]), fmaxf(s[2], s[3]));
        float mn = fmaxf(m, bm);
        float corr = __expf(m - mn);
        Z *= corr;
        agg.x *= corr; agg.y *= corr; agg.z *= corr; agg.w *= corr;
        m = mn;
        #pragma unroll
        for (int j = 0; j < RB; ++j) {
            float e = __expf(s[j] - mn);
            Z += e;
            float4 v = sRow[warp][j * 32 + lane];
            agg.x += e * v.x; agg.y += e * v.y;
            agg.z += e * v.z; agg.w += e * v.w;
        }
        __syncwarp();
    }
    {
        float iz = 1.0f / Z;
        agg.x *= iz; agg.y *= iz; agg.z *= iz; agg.w *= iz;
    }

    // ---- stage agg; output GEMMs: lane covers output cols [4*lane, 4*lane+4) ----
    sRow[warp][lane] = agg;
    __syncwarp();
    const float* aggf = reinterpret_cast<const float*>(&sRow[warp][0]);
    const float* xf   = reinterpret_cast<const float*>(&sX[warp][0]);

    u64 y1a = 0ull, y1b = 0ull, y2a = 0ull, y2b = 0ull;
    const float4* wn4 = reinterpret_cast<const float4*>(W_node);
    const float4* wb4 = reinterpret_cast<const float4*>(W_neib);
    #pragma unroll 4
    for (int d = 0; d < D; ++d) {
        float xn = xf[d];
        float xa = aggf[d];
        u64 xn2 = pack2(xn, xn);
        u64 xa2 = pack2(xa, xa);
        float4 wv1 = wn4[d * 32 + lane];
        float4 wv2 = wb4[d * 32 + lane];
        y1a = ffma2(xn2, pack2(wv1.x, wv1.y), y1a);
        y1b = ffma2(xn2, pack2(wv1.z, wv1.w), y1b);
        y2a = ffma2(xa2, pack2(wv2.x, wv2.y), y2a);
        y2b = ffma2(xa2, pack2(wv2.z, wv2.w), y2b);
    }

    float2 f1a = unpack2(y1a), f1b = unpack2(y1b);
    float2 f2a = unpack2(y2a), f2b = unpack2(y2b);
    float4 o1 = make_float4(fmaxf(f1a.x, 0.f), fmaxf(f1a.y, 0.f),
                            fmaxf(f1b.x, 0.f), fmaxf(f1b.y, 0.f));
    float4 o2 = make_float4(fmaxf(f2a.x, 0.f), fmaxf(f2a.y, 0.f),
                            fmaxf(f2b.x, 0.f), fmaxf(f2b.y, 0.f));

    float4* orow = reinterpret_cast<float4*>(out + (size_t)node * (2 * O));
    orow[lane]      = o1;   // cols [0,128)
    orow[32 + lane] = o2;   // cols [128,256)
}

extern "C" void kernel_launch(void* const* d_in, const int* in_sizes, int n_in,
                              void* d_out, int out_size) {
    const float* node_feats = (const float*)d_in[0];
    const float* neib_feats = (const float*)d_in[1];
    // d_in[2] = node_ids, d_in[3] = neib_ids : unused by the reference computation
    const float* W_att1 = (const float*)d_in[4];
    const float* W_att2 = (const float*)d_in[5];
    const float* W_node = (const float*)d_in[6];
    const float* W_neib = (const float*)d_in[7];

    int n = in_sizes[0] / D;
    int blocks = (n + WARPS - 1) / WARPS;
    attn_agg_kernel<<<blocks, NTHREADS>>>(node_feats, neib_feats,
                                          W_att1, W_att2, W_node, W_neib,
                                          (float*)d_out, n);
}

// round 4
// speedup vs baseline: 1.0030x; 1.0030x over previous
#include <cuda_runtime.h>

typedef unsigned long long u64;

constexpr int D = 128;   // feature dim
constexpr int K = 32;    // neighbors per node
constexpr int H = 32;    // attention hidden
constexpr int O = 128;   // output dim per branch
constexpr int WARPS = 8;            // nodes per block (1 warp per node)
constexpr int NTHREADS = WARPS * 32;
constexpr int RB = 4;               // neighbor rows per batch
constexpr int NBATCH = K / RB;      // 8

__device__ __forceinline__ u64 pack2(float lo, float hi) {
    u64 r; asm("mov.b64 %0, {%1, %2};" : "=l"(r) : "f"(lo), "f"(hi)); return r;
}
__device__ __forceinline__ float2 unpack2(u64 v) {
    float2 f; asm("mov.b64 {%0, %1}, %2;" : "=f"(f.x), "=f"(f.y) : "l"(v)); return f;
}
// d = a*b + c (packed 2 x f32)
__device__ __forceinline__ u64 ffma2(u64 a, u64 b, u64 c) {
    u64 d; asm("fma.rn.f32x2 %0, %1, %2, %3;" : "=l"(d) : "l"(a), "l"(b), "l"(c)); return d;
}
__device__ __forceinline__ float warp_sum(float v) {
    #pragma unroll
    for (int o = 16; o > 0; o >>= 1) v += __shfl_xor_sync(0xffffffffu, v, o);
    return v;
}

__global__ __launch_bounds__(NTHREADS)
void attn_agg_kernel(const float* __restrict__ node_feats,
                     const float* __restrict__ neib_feats,
                     const float* __restrict__ W_att1,   // [D,H] row-major
                     const float* __restrict__ W_att2,   // [H,H] row-major
                     const float* __restrict__ W_node,   // [D,O] row-major
                     const float* __restrict__ W_neib,   // [D,O] row-major
                     float* __restrict__ out,            // [N, 2*O]
                     int n)
{
    // sW1[p*32+h] = {W_att1[2p][h], W_att1[2p+1][h]}  (d-pair packed for f32x2)
    __shared__ u64    sW1[64 * 32];        // 16 KB
    __shared__ float  sW2[32 * 33];        // padded stride 33 (conflict-free both ways)
    __shared__ float4 sRow[WARPS][RB * 32];// 16 KB: per-warp neighbor batch
    __shared__ float4 sX[WARPS][32];       // 4 KB: per-warp node row
    __shared__ float  sT[WARPS][32];       // per-warp H-vector scratch

    const int tid  = threadIdx.x;
    const int lane = tid & 31;
    const int warp = tid >> 5;

    for (int i = tid; i < 64 * 32; i += NTHREADS) {
        int p = i >> 5, h = i & 31;
        sW1[i] = pack2(W_att1[(2 * p) * H + h], W_att1[(2 * p + 1) * H + h]);
    }
    for (int i = tid; i < 32 * 32; i += NTHREADS) {
        sW2[(i >> 5) * 33 + (i & 31)] = W_att2[i];
    }
    __syncthreads();

    const int node = blockIdx.x * WARPS + warp;
    if (node >= n) return;

    const float* nrow = node_feats + (size_t)node * D;
    const float* nb   = neib_feats + (size_t)node * (K * D);

    // ---- stage node row ----
    sX[warp][lane] = reinterpret_cast<const float4*>(nrow)[lane];
    __syncwarp();
    const u64* x64 = reinterpret_cast<const u64*>(&sX[warp][0]);

    // ---- t_node[lane] = tanh(node_row . W1[:,lane]) ----
    u64 a01 = 0ull, a23 = 0ull;
    #pragma unroll
    for (int d0 = 0; d0 < 32; ++d0) {
        u64 w01 = sW1[(2 * d0) * 32 + lane];
        u64 w23 = sW1[(2 * d0 + 1) * 32 + lane];
        a01 = ffma2(x64[2 * d0],     w01, a01);
        a23 = ffma2(x64[2 * d0 + 1], w23, a23);
    }
    {
        float2 qa = unpack2(a01), qb = unpack2(a23);
        sT[warp][lane] = tanhf(qa.x + qa.y + qb.x + qb.y);
    }
    __syncwarp();

    // ---- node_att[lane] = sum_h' t_node[h'] * W2[h'][lane] ----
    float na = 0.f;
    #pragma unroll
    for (int h = 0; h < 32; ++h) na += sT[warp][h] * sW2[h * 33 + lane];
    __syncwarp();
    sT[warp][lane] = na;
    __syncwarp();

    // ---- u[lane] = sum_h W2[lane][h] * node_att[h]  (folds W2 out of the K loop) ----
    float u = 0.f;
    #pragma unroll
    for (int h = 0; h < 32; ++h) u += sW2[lane * 33 + h] * sT[warp][h];

    // ---- neighbor loop: scores + online softmax + weighted aggregation, one pass ----
    float m = -1e30f, Z = 0.f;
    float4 agg = make_float4(0.f, 0.f, 0.f, 0.f);
    const u64* r64 = reinterpret_cast<const u64*>(&sRow[warp][0]);

    // prefetch batch 0
    float4 pre[RB];
    #pragma unroll
    for (int j = 0; j < RB; ++j)
        pre[j] = reinterpret_cast<const float4*>(nb + (size_t)j * D)[lane];

    #pragma unroll 1
    for (int b = 0; b < NBATCH; ++b) {
        #pragma unroll
        for (int j = 0; j < RB; ++j) sRow[warp][j * 32 + lane] = pre[j];
        __syncwarp();

        if (b + 1 < NBATCH) {
            #pragma unroll
            for (int j = 0; j < RB; ++j)
                pre[j] = reinterpret_cast<const float4*>(
                             nb + (size_t)((b + 1) * RB + j) * D)[lane];
        }

        u64 acc01[RB], acc23[RB];
        #pragma unroll
        for (int j = 0; j < RB; ++j) { acc01[j] = 0ull; acc23[j] = 0ull; }

        #pragma unroll
        for (int d0 = 0; d0 < 32; ++d0) {
            u64 w01 = sW1[(2 * d0) * 32 + lane];
            u64 w23 = sW1[(2 * d0 + 1) * 32 + lane];
            #pragma unroll
            for (int j = 0; j < RB; ++j) {
                acc01[j] = ffma2(r64[j * 64 + 2 * d0],     w01, acc01[j]);
                acc23[j] = ffma2(r64[j * 64 + 2 * d0 + 1], w23, acc23[j]);
            }
        }

        float s[RB];
        #pragma unroll
        for (int j = 0; j < RB; ++j) {
            float2 q0 = unpack2(acc01[j]), q1 = unpack2(acc23[j]);
            float t = tanhf(q0.x + q0.y + q1.x + q1.y);
            s[j] = warp_sum(t * u);      // score for neighbor b*RB+j (all lanes)
        }

        float bm = fmaxf(fmaxf(s[0], s[1]), fmaxf(s[2], s[3]));
        float mn = fmaxf(m, bm);
        float corr = __expf(m - mn);
        Z *= corr;
        agg.x *= corr; agg.y *= corr; agg.z *= corr; agg.w *= corr;
        m = mn;
        #pragma unroll
        for (int j = 0; j < RB; ++j) {
            float e = __expf(s[j] - mn);
            Z += e;
            float4 v = sRow[warp][j * 32 + lane];
            agg.x += e * v.x; agg.y += e * v.y;
            agg.z += e * v.z; agg.w += e * v.w;
        }
        __syncwarp();
    }
    {
        float iz = 1.0f / Z;
        agg.x *= iz; agg.y *= iz; agg.z *= iz; agg.w *= iz;
    }

    // ---- stage agg; output GEMMs: lane covers output cols [4*lane, 4*lane+4) ----
    sRow[warp][lane] = agg;
    __syncwarp();
    const float* aggf = reinterpret_cast<const float*>(&sRow[warp][0]);
    const float* xf   = reinterpret_cast<const float*>(&sX[warp][0]);

    u64 y1a = 0ull, y1b = 0ull, y2a = 0ull, y2b = 0ull;
    const float4* wn4 = reinterpret_cast<const float4*>(W_node);
    const float4* wb4 = reinterpret_cast<const float4*>(W_neib);
    #pragma unroll 4
    for (int d = 0; d < D; ++d) {
        float xn = xf[d];
        float xa = aggf[d];
        u64 xn2 = pack2(xn, xn);
        u64 xa2 = pack2(xa, xa);
        float4 wv1 = wn4[d * 32 + lane];
        float4 wv2 = wb4[d * 32 + lane];
        y1a = ffma2(xn2, pack2(wv1.x, wv1.y), y1a);
        y1b = ffma2(xn2, pack2(wv1.z, wv1.w), y1b);
        y2a = ffma2(xa2, pack2(wv2.x, wv2.y), y2a);
        y2b = ffma2(xa2, pack2(wv2.z, wv2.w), y2b);
    }

    float2 f1a = unpack2(y1a), f1b = unpack2(y1b);
    float2 f2a = unpack2(y2a), f2b = unpack2(y2b);
    float4 o1 = make_float4(fmaxf(f1a.x, 0.f), fmaxf(f1a.y, 0.f),
                            fmaxf(f1b.x, 0.f), fmaxf(f1b.y, 0.f));
    float4 o2 = make_float4(fmaxf(f2a.x, 0.f), fmaxf(f2a.y, 0.f),
                            fmaxf(f2b.x, 0.f), fmaxf(f2b.y, 0.f));

    float4* orow = reinterpret_cast<float4*>(out + (size_t)node * (2 * O));
    orow[lane]      = o1;   // cols [0,128)
    orow[32 + lane] = o2;   // cols [128,256)
}

extern "C" void kernel_launch(void* const* d_in, const int* in_sizes, int n_in,
                              void* d_out, int out_size) {
    const float* node_feats = (const float*)d_in[0];
    const float* neib_feats = (const float*)d_in[1];
    // d_in[2] = node_ids, d_in[3] = neib_ids : unused by the reference computation
    const float* W_att1 = (const float*)d_in[4];
    const float* W_att2 = (const float*)d_in[5];
    const float* W_node = (const float*)d_in[6];
    const float* W_neib = (const float*)d_in[7];

    int n = in_sizes[0] / D;
    int blocks = (n + WARPS - 1) / WARPS;
    attn_agg_kernel<<<blocks, NTHREADS>>>(node_feats, neib_feats,
                                          W_att1, W_att2, W_node, W_neib,
                                          (float*)d_out, n);
}

// round 5
// speedup vs baseline: 1.6441x; 1.6391x over previous
#include <cuda_runtime.h>

typedef unsigned long long u64;

constexpr int D = 128;   // feature dim
constexpr int K = 32;    // neighbors per node
constexpr int H = 32;    // attention hidden
constexpr int O = 128;   // output dim per branch
constexpr int WARPS = 8;            // nodes per block (1 warp per node)
constexpr int NTHREADS = WARPS * 32;
constexpr int RB = 4;               // neighbor rows per batch
constexpr int NBATCH = K / RB;      // 8

__device__ __forceinline__ u64 pack2(float lo, float hi) {
    u64 r; asm("mov.b64 %0, {%1, %2};" : "=l"(r) : "f"(lo), "f"(hi)); return r;
}
__device__ __forceinline__ float2 unpack2(u64 v) {
    float2 f; asm("mov.b64 {%0, %1}, %2;" : "=f"(f.x), "=f"(f.y) : "l"(v)); return f;
}
// d = a*b + c (packed 2 x f32)
__device__ __forceinline__ u64 ffma2(u64 a, u64 b, u64 c) {
    u64 d; asm("fma.rn.f32x2 %0, %1, %2, %3;" : "=l"(d) : "l"(a), "l"(b), "l"(c)); return d;
}
__device__ __forceinline__ float warp_sum(float v) {
    #pragma unroll
    for (int o = 16; o > 0; o >>= 1) v += __shfl_xor_sync(0xffffffffu, v, o);
    return v;
}

__global__ __launch_bounds__(NTHREADS)
void attn_agg_kernel(const float* __restrict__ node_feats,
                     const float* __restrict__ neib_feats,
                     const float* __restrict__ W_att1,   // [D,H] row-major
                     const float* __restrict__ W_att2,   // [H,H] row-major
                     const float* __restrict__ W_node,   // [D,O] row-major
                     const float* __restrict__ W_neib,   // [D,O] row-major
                     float* __restrict__ out,            // [N, 2*O]
                     int n)
{
    // sW1[p*32+h] = {W_att1[2p][h], W_att1[2p+1][h]}  (d-pair packed for f32x2)
    __shared__ u64    sW1[64 * 32];        // 16 KB
    __shared__ float  sW2[32 * 33];        // padded stride 33 (conflict-free both ways)
    __shared__ float4 sRow[WARPS][RB * 32];// 16 KB: per-warp neighbor batch
    __shared__ float4 sX[WARPS][32];       // 4 KB: per-warp node row
    __shared__ float  sT[WARPS][32];       // per-warp H-vector scratch

    const int tid  = threadIdx.x;
    const int lane = tid & 31;
    const int warp = tid >> 5;

    for (int i = tid; i < 64 * 32; i += NTHREADS) {
        int p = i >> 5, h = i & 31;
        sW1[i] = pack2(W_att1[(2 * p) * H + h], W_att1[(2 * p + 1) * H + h]);
    }
    for (int i = tid; i < 32 * 32; i += NTHREADS) {
        sW2[(i >> 5) * 33 + (i & 31)] = W_att2[i];
    }
    __syncthreads();

    const int node = blockIdx.x * WARPS + warp;
    if (node >= n) return;

    const float* nrow = node_feats + (size_t)node * D;
    const float* nb   = neib_feats + (size_t)node * (K * D);

    // ---- stage node row ----
    sX[warp][lane] = reinterpret_cast<const float4*>(nrow)[lane];
    __syncwarp();
    const u64* x64 = reinterpret_cast<const u64*>(&sX[warp][0]);

    // ---- t_node[lane] = tanh(node_row . W1[:,lane]) ----
    u64 a01 = 0ull, a23 = 0ull;
    #pragma unroll
    for (int d0 = 0; d0 < 32; ++d0) {
        u64 w01 = sW1[(2 * d0) * 32 + lane];
        u64 w23 = sW1[(2 * d0 + 1) * 32 + lane];
        a01 = ffma2(x64[2 * d0],     w01, a01);
        a23 = ffma2(x64[2 * d0 + 1], w23, a23);
    }
    {
        float2 qa = unpack2(a01), qb = unpack2(a23);
        sT[warp][lane] = tanhf(qa.x + qa.y + qb.x + qb.y);
    }
    __syncwarp();

    // ---- node_att[lane] = sum_h' t_node[h'] * W2[h'][lane] ----
    float na = 0.f;
    #pragma unroll
    for (int h = 0; h < 32; ++h) na += sT[warp][h] * sW2[h * 33 + lane];
    __syncwarp();
    sT[warp][lane] = na;
    __syncwarp();

    // ---- u[lane] = sum_h W2[lane][h] * node_att[h]  (folds W2 out of the K loop) ----
    float u = 0.f;
    #pragma unroll
    for (int h = 0; h < 32; ++h) u += sW2[lane * 33 + h] * sT[warp][h];

    // ---- neighbor loop: scores + online softmax + weighted aggregation, one pass ----
    float m = -1e30f, Z = 0.f;
    float4 agg = make_float4(0.f, 0.f, 0.f, 0.f);
    const u64* r64 = reinterpret_cast<const u64*>(&sRow[warp][0]);

    // prefetch batch 0
    float4 pre[RB];
    #pragma unroll
    for (int j = 0; j < RB; ++j)
        pre[j] = reinterpret_cast<const float4*>(nb + (size_t)j * D)[lane];

    #pragma unroll 1
    for (int b = 0; b < NBATCH; ++b) {
        #pragma unroll
        for (int j = 0; j < RB; ++j) sRow[warp][j * 32 + lane] = pre[j];
        __syncwarp();

        if (b + 1 < NBATCH) {
            #pragma unroll
            for (int j = 0; j < RB; ++j)
                pre[j] = reinterpret_cast<const float4*>(
                             nb + (size_t)((b + 1) * RB + j) * D)[lane];
        }

        u64 acc01[RB], acc23[RB];
        #pragma unroll
        for (int j = 0; j < RB; ++j) { acc01[j] = 0ull; acc23[j] = 0ull; }

        #pragma unroll
        for (int d0 = 0; d0 < 32; ++d0) {
            u64 w01 = sW1[(2 * d0) * 32 + lane];
            u64 w23 = sW1[(2 * d0 + 1) * 32 + lane];
            #pragma unroll
            for (int j = 0; j < RB; ++j) {
                acc01[j] = ffma2(r64[j * 64 + 2 * d0],     w01, acc01[j]);
                acc23[j] = ffma2(r64[j * 64 + 2 * d0 + 1], w23, acc23[j]);
            }
        }

        float s[RB];
        #pragma unroll
        for (int j = 0; j < RB; ++j) {
            float2 q0 = unpack2(acc01[j]), q1 = unpack2(acc23[j]);
            float t = tanhf(q0.x + q0.y + q1.x + q1.y);
            s[j] = warp_sum(t * u);      // score for neighbor b*RB+j (all lanes)
        }

        float bm = fmaxf(fmaxf(s[0], s[1]), fmaxf(s[2], s[3]));
        float mn = fmaxf(m, bm);
        float corr = __expf(m - mn);
        Z *= corr;
        agg.x *= corr; agg.y *= corr; agg.z *= corr; agg.w *= corr;
        m = mn;
        #pragma unroll
        for (int j = 0; j < RB; ++j) {
            float e = __expf(s[j] - mn);
            Z += e;
            float4 v = sRow[warp][j * 32 + lane];
            agg.x += e * v.x; agg.y += e * v.y;
            agg.z += e * v.z; agg.w += e * v.w;
        }
        __syncwarp();
    }
    {
        float iz = 1.0f / Z;
        agg.x *= iz; agg.y *= iz; agg.z *= iz; agg.w *= iz;
    }

    // ---- stage agg; output GEMMs: lane covers output cols [4*lane, 4*lane+4) ----
    sRow[warp][lane] = agg;
    __syncwarp();
    const float* aggf = reinterpret_cast<const float*>(&sRow[warp][0]);
    const float* xf   = reinterpret_cast<const float*>(&sX[warp][0]);

    u64 y1a = 0ull, y1b = 0ull, y2a = 0ull, y2b = 0ull;
    const float4* wn4 = reinterpret_cast<const float4*>(W_node);
    const float4* wb4 = reinterpret_cast<const float4*>(W_neib);
    #pragma unroll 4
    for (int d = 0; d < D; ++d) {
        float xn = xf[d];
        float xa = aggf[d];
        u64 xn2 = pack2(xn, xn);
        u64 xa2 = pack2(xa, xa);
        float4 wv1 = wn4[d * 32 + lane];
        float4 wv2 = wb4[d * 32 + lane];
        y1a = ffma2(xn2, pack2(wv1.x, wv1.y), y1a);
        y1b = ffma2(xn2, pack2(wv1.z, wv1.w), y1b);
        y2a = ffma2(xa2, pack2(wv2.x, wv2.y), y2a);
        y2b = ffma2(xa2, pack2(wv2.z, wv2.w), y2b);
    }

    float2 f1a = unpack2(y1a), f1b = unpack2(y1b);
    float2 f2a = unpack2(y2a), f2b = unpack2(y2b);
    float4 o1 = make_float4(fmaxf(f1a.x, 0.f), fmaxf(f1a.y, 0.f),
                            fmaxf(f1b.x, 0.f), fmaxf(f1b.y, 0.f));
    float4 o2 = make_float4(fmaxf(f2a.x, 0.f), fmaxf(f2a.y, 0.f),
                            fmaxf(f2b.x, 0.f), fmaxf(f2b.y, 0.f));

    float4* orow = reinterpret_cast<float4*>(out + (size_t)node * (2 * O));
    orow[lane]      = o1;   // cols [0,128)
    orow[32 + lane] = o2;   // cols [128,256)
}

extern "C" void kernel_launch(void* const* d_in, const int* in_sizes, int n_in,
                              void* d_out, int out_size) {
    const float* node_feats = (const float*)d_in[0];
    const float* neib_feats = (const float*)d_in[1];
    // d_in[2] = node_ids, d_in[3] = neib_ids : unused by the reference computation
    const float* W_att1 = (const float*)d_in[4];
    const float* W_att2 = (const float*)d_in[5];
    const float* W_node = (const float*)d_in[6];
    const float* W_neib = (const float*)d_in[7];

    int n = in_sizes[0] / D;
    int blocks = (n + WARPS - 1) / WARPS;
    attn_agg_kernel<<<blocks, NTHREADS>>>(node_feats, neib_feats,
                                          W_att1, W_att2, W_node, W_neib,
                                          (float*)d_out, n);
}

// round 6
// speedup vs baseline: 2.0009x; 1.2171x over previous
#include <cuda_runtime.h>

typedef unsigned long long u64;

constexpr int D = 128;   // feature dim
constexpr int K = 32;    // neighbors per node
constexpr int H = 32;    // attention hidden
constexpr int O = 128;   // output dim per branch
constexpr int WARPS = 8;            // nodes per block (1 warp per node)
constexpr int NTHREADS = WARPS * 32;
constexpr int RB = 8;               // neighbor rows per batch
constexpr int NBATCH = K / RB;      // 4

// Repacked W_att1: W1q[q][h] = d-quad (4q..4q+3) of column h, as 2 packed f32x2.
__device__ ulonglong2 g_W1q[32 * 32];

__device__ __forceinline__ u64 pack2(float lo, float hi) {
    u64 r; asm("mov.b64 %0, {%1, %2};" : "=l"(r) : "f"(lo), "f"(hi)); return r;
}
__device__ __forceinline__ float2 unpack2(u64 v) {
    float2 f; asm("mov.b64 {%0, %1}, %2;" : "=f"(f.x), "=f"(f.y) : "l"(v)); return f;
}
__device__ __forceinline__ u64 ffma2(u64 a, u64 b, u64 c) {
    u64 d; asm("fma.rn.f32x2 %0, %1, %2, %3;" : "=l"(d) : "l"(a), "l"(b), "l"(c)); return d;
}
__device__ __forceinline__ float warp_sum(float v) {
    #pragma unroll
    for (int o = 16; o > 0; o >>= 1) v += __shfl_xor_sync(0xffffffffu, v, o);
    return v;
}
__device__ __forceinline__ float fc(const float4& v, int i) {
    return i == 0 ? v.x : (i == 1 ? v.y : (i == 2 ? v.z : v.w));
}

__global__ void repack_w1_kernel(const float* __restrict__ W_att1) {
    int i = threadIdx.x;             // 1024 threads, one block
    if (i < 32 * 32) {
        int q = i >> 5, h = i & 31;
        ulonglong2 w;
        w.x = pack2(W_att1[(4 * q + 0) * H + h], W_att1[(4 * q + 1) * H + h]);
        w.y = pack2(W_att1[(4 * q + 2) * H + h], W_att1[(4 * q + 3) * H + h]);
        g_W1q[i] = w;
    }
}

__global__ __launch_bounds__(NTHREADS)
void attn_agg_kernel(const float* __restrict__ node_feats,
                     const float* __restrict__ neib_feats,
                     const float* __restrict__ W_att2,   // [H,H] row-major
                     const float* __restrict__ W_node,   // [D,O] row-major
                     const float* __restrict__ W_neib,   // [D,O] row-major
                     float* __restrict__ out,            // [N, 2*O]
                     int n)
{
    __shared__ float4 sRow[WARPS][RB * 32];  // 32 KB: per-warp neighbor batch
    __shared__ float  sW2[32 * 33];          // 4.2 KB, padded stride 33
    __shared__ float4 sX[WARPS][32];         // 4 KB: node rows
    __shared__ float4 sAgg[WARPS][32];       // 4 KB: aggregated neighbor rows
    __shared__ float  sT[WARPS][32];         // per-warp H-vector scratch

    const int tid  = threadIdx.x;
    const int lane = tid & 31;
    const int warp = tid >> 5;

    for (int i = tid; i < 32 * 32; i += NTHREADS)
        sW2[(i >> 5) * 33 + (i & 31)] = W_att2[i];
    __syncthreads();

    const int node = blockIdx.x * WARPS + warp;

    if (node < n) {
        const float* nrow = node_feats + (size_t)node * D;
        const float* nb   = neib_feats + (size_t)node * (K * D);
        const float4* nb4 = reinterpret_cast<const float4*>(nb);

        // ---- stage node row ----
        sX[warp][lane] = reinterpret_cast<const float4*>(nrow)[lane];
        __syncwarp();

        // ---- t_node[lane] = tanh(node_row . W1[:,lane]) ----
        u64 a = 0ull;
        #pragma unroll
        for (int q = 0; q < 32; ++q) {
            ulonglong2 w = g_W1q[q * 32 + lane];   // LDG.128, L1-hot
            float4 xv = sX[warp][q];               // broadcast LDS.128
            a = ffma2(pack2(xv.x, xv.y), w.x, a);
            a = ffma2(pack2(xv.z, xv.w), w.y, a);
        }
        {
            float2 qa = unpack2(a);
            sT[warp][lane] = tanhf(qa.x + qa.y);
        }
        __syncwarp();

        // ---- node_att[lane] = sum_h t[h] * W2[h][lane] ----
        float na = 0.f;
        #pragma unroll
        for (int h = 0; h < 32; ++h) na += sT[warp][h] * sW2[h * 33 + lane];
        __syncwarp();
        sT[warp][lane] = na;
        __syncwarp();

        // ---- u[lane] = sum_h W2[lane][h] * node_att[h] ----
        float u = 0.f;
        #pragma unroll
        for (int h = 0; h < 32; ++h) u += sW2[lane * 33 + h] * sT[warp][h];

        // ---- neighbor loop: scores + online softmax + aggregation ----
        float m = -1e30f, Z = 0.f;
        float4 agg = make_float4(0.f, 0.f, 0.f, 0.f);

        #pragma unroll 1
        for (int b = 0; b < NBATCH; ++b) {
            // stage RB rows (LDG.128 -> STS.128)
            #pragma unroll
            for (int j = 0; j < RB; ++j)
                sRow[warp][j * 32 + lane] = nb4[(size_t)(b * RB + j) * 32 + lane];
            __syncwarp();

            u64 acc[RB];
            #pragma unroll
            for (int j = 0; j < RB; ++j) acc[j] = 0ull;

            #pragma unroll
            for (int q = 0; q < 32; ++q) {
                ulonglong2 w = g_W1q[q * 32 + lane];   // LDG.128
                #pragma unroll
                for (int j = 0; j < RB; ++j) {
                    float4 rv = sRow[warp][j * 32 + q]; // broadcast LDS.128
                    acc[j] = ffma2(pack2(rv.x, rv.y), w.x, acc[j]);
                    acc[j] = ffma2(pack2(rv.z, rv.w), w.y, acc[j]);
                }
            }

            float s[RB];
            #pragma unroll
            for (int j = 0; j < RB; ++j) {
                float2 qq = unpack2(acc[j]);
                float t = tanhf(qq.x + qq.y);
                s[j] = warp_sum(t * u);
            }

            float bm = s[0];
            #pragma unroll
            for (int j = 1; j < RB; ++j) bm = fmaxf(bm, s[j]);
            float mn = fmaxf(m, bm);
            float corr = __expf(m - mn);
            Z *= corr;
            agg.x *= corr; agg.y *= corr; agg.z *= corr; agg.w *= corr;
            m = mn;
            #pragma unroll
            for (int j = 0; j < RB; ++j) {
                float e = __expf(s[j] - mn);
                Z += e;
                float4 v = sRow[warp][j * 32 + lane];   // lane-indexed LDS.128
                agg.x += e * v.x; agg.y += e * v.y;
                agg.z += e * v.z; agg.w += e * v.w;
            }
            __syncwarp();
        }
        {
            float iz = 1.0f / Z;
            agg.x *= iz; agg.y *= iz; agg.z *= iz; agg.w *= iz;
        }
        sAgg[warp][lane] = agg;
    }

    // ================= block-cooperative epilogue =================
    // Thread t owns one output column for ALL 8 nodes of the block:
    //   t in [0,128): col t of x @ W_node      (reads sX)
    //   t in [128,256): col t-128 of agg @ W_neib (reads sAgg)
    // Weights are read once per block (coalesced LDG.32 per warp per d).
    __syncthreads();

    const bool useAgg = (tid >= 128);                    // warp-uniform
    const int  col    = tid & 127;
    const float* __restrict__ Wsel = useAgg ? W_neib : W_node;
    const float4 (*src)[32] = useAgg ? sAgg : sX;

    u64 acc2[4] = {0ull, 0ull, 0ull, 0ull};              // node pairs (0,1)(2,3)(4,5)(6,7)

    #pragma unroll 2
    for (int q = 0; q < 32; ++q) {
        float4 sv[8];
        #pragma unroll
        for (int w = 0; w < 8; ++w) sv[w] = src[w][q];   // broadcast LDS.128
        #pragma unroll
        for (int i = 0; i < 4; ++i) {
            float wv = Wsel[(size_t)(4 * q + i) * O + col];  // coalesced LDG.32
            u64 wv2 = pack2(wv, wv);
            acc2[0] = ffma2(pack2(fc(sv[0], i), fc(sv[1], i)), wv2, acc2[0]);
            acc2[1] = ffma2(pack2(fc(sv[2], i), fc(sv[3], i)), wv2, acc2[1]);
            acc2[2] = ffma2(pack2(fc(sv[4], i), fc(sv[5], i)), wv2, acc2[2]);
            acc2[3] = ffma2(pack2(fc(sv[6], i), fc(sv[7], i)), wv2, acc2[3]);
        }
    }

    const int base = blockIdx.x * WARPS;
    const int oc   = col + (useAgg ? O : 0);
    #pragma unroll
    for (int p = 0; p < 4; ++p) {
        float2 f = unpack2(acc2[p]);
        int n0 = base + 2 * p, n1 = n0 + 1;
        if (n0 < n) out[(size_t)n0 * (2 * O) + oc] = fmaxf(f.x, 0.f);
        if (n1 < n) out[(size_t)n1 * (2 * O) + oc] = fmaxf(f.y, 0.f);
    }
}

extern "C" void kernel_launch(void* const* d_in, const int* in_sizes, int n_in,
                              void* d_out, int out_size) {
    const float* node_feats = (const float*)d_in[0];
    const float* neib_feats = (const float*)d_in[1];
    // d_in[2] = node_ids, d_in[3] = neib_ids : unused by the reference computation
    const float* W_att1 = (const float*)d_in[4];
    const float* W_att2 = (const float*)d_in[5];
    const float* W_node = (const float*)d_in[6];
    const float* W_neib = (const float*)d_in[7];

    int n = in_sizes[0] / D;
    repack_w1_kernel<<<1, 1024>>>(W_att1);
    int blocks = (n + WARPS - 1) / WARPS;
    attn_agg_kernel<<<blocks, NTHREADS>>>(node_feats, neib_feats,
                                          W_att2, W_node, W_neib,
                                          (float*)d_out, n);
}

// round 7
// speedup vs baseline: 2.0822x; 1.0406x over previous
#include <cuda_runtime.h>

typedef unsigned long long u64;

constexpr int D = 128;   // feature dim
constexpr int K = 32;    // neighbors per node
constexpr int H = 32;    // attention hidden
constexpr int O = 128;   // output dim per branch
constexpr int WARPS = 8;            // nodes per block (1 warp per node)
constexpr int NTHREADS = WARPS * 32;
constexpr int RB = 8;               // neighbor rows per batch
constexpr int NBATCH = K / RB;      // 4
constexpr int RSTRIDE = 33;         // float4 units per staged row (528B, bank-pad)

// Old layout (node-att phase): W1q[q][h] = d-quad (4q..4q+3) of column h.
__device__ ulonglong2 g_W1q[32 * 32];
// New layout (main loop): gW2[q*32 + i*8 + c] =
//   { pack2(W1[4q+i][c], W1[4q+i][c+8]), pack2(W1[4q+i][c+16], W1[4q+i][c+24]) }
__device__ ulonglong2 g_W2q[32 * 4 * 8];

__device__ __forceinline__ u64 pack2(float lo, float hi) {
    u64 r; asm("mov.b64 %0, {%1, %2};" : "=l"(r) : "f"(lo), "f"(hi)); return r;
}
__device__ __forceinline__ float2 unpack2(u64 v) {
    float2 f; asm("mov.b64 {%0, %1}, %2;" : "=f"(f.x), "=f"(f.y) : "l"(v)); return f;
}
__device__ __forceinline__ u64 ffma2(u64 a, u64 b, u64 c) {
    u64 d; asm("fma.rn.f32x2 %0, %1, %2, %3;" : "=l"(d) : "l"(a), "l"(b), "l"(c)); return d;
}
__device__ __forceinline__ float fc(const float4& v, int i) {
    return i == 0 ? v.x : (i == 1 ? v.y : (i == 2 ? v.z : v.w));
}

__global__ void repack_w1_kernel(const float* __restrict__ W_att1) {
    int i = threadIdx.x;             // 1024 threads, one block
    if (i < 32 * 32) {
        int q = i >> 5, h = i & 31;
        ulonglong2 w;
        w.x = pack2(W_att1[(4 * q + 0) * H + h], W_att1[(4 * q + 1) * H + h]);
        w.y = pack2(W_att1[(4 * q + 2) * H + h], W_att1[(4 * q + 3) * H + h]);
        g_W1q[i] = w;
        // new layout
        int q2 = i >> 5, r = i & 31;
        int ii = r >> 3, c = r & 7;
        int d = 4 * q2 + ii;
        ulonglong2 w2;
        w2.x = pack2(W_att1[d * H + c],      W_att1[d * H + c + 8]);
        w2.y = pack2(W_att1[d * H + c + 16], W_att1[d * H + c + 24]);
        g_W2q[q2 * 32 + ii * 8 + c] = w2;
    }
}

__global__ __launch_bounds__(NTHREADS, 3)
void attn_agg_kernel(const float* __restrict__ node_feats,
                     const float* __restrict__ neib_feats,
                     const float* __restrict__ W_att2,   // [H,H] row-major
                     const float* __restrict__ W_node,   // [D,O] row-major
                     const float* __restrict__ W_neib,   // [D,O] row-major
                     float* __restrict__ out,            // [N, 2*O]
                     int n)
{
    __shared__ float4 sRow[WARPS][RB * RSTRIDE]; // 33.8 KB: padded neighbor batch
    __shared__ float  sW2[32 * 33];              // 4.2 KB
    __shared__ float4 sX[WARPS][32];             // 4 KB: node rows
    __shared__ float4 sAgg[WARPS][32];           // 4 KB: aggregated rows
    __shared__ float  sT[WARPS][32];             // per-warp H-vector scratch

    const int tid  = threadIdx.x;
    const int lane = tid & 31;
    const int warp = tid >> 5;

    for (int i = tid; i < 32 * 32; i += NTHREADS)
        sW2[(i >> 5) * 33 + (i & 31)] = W_att2[i];
    __syncthreads();

    const int node = blockIdx.x * WARPS + warp;

    if (node < n) {
        const float* nrow = node_feats + (size_t)node * D;
        const float4* nb4 = reinterpret_cast<const float4*>(
                                neib_feats + (size_t)node * (K * D));

        // ---- stage node row ----
        sX[warp][lane] = reinterpret_cast<const float4*>(nrow)[lane];
        __syncwarp();

        // ---- t_node[lane] = tanh(node_row . W1[:,lane])  (lane = h layout) ----
        u64 a = 0ull;
        #pragma unroll
        for (int q = 0; q < 32; ++q) {
            ulonglong2 w = g_W1q[q * 32 + lane];
            float4 xv = sX[warp][q];
            a = ffma2(pack2(xv.x, xv.y), w.x, a);
            a = ffma2(pack2(xv.z, xv.w), w.y, a);
        }
        {
            float2 qa = unpack2(a);
            sT[warp][lane] = tanhf(qa.x + qa.y);
        }
        __syncwarp();

        // ---- node_att[lane] = sum_h t[h] * W2[h][lane] ----
        float na = 0.f;
        #pragma unroll
        for (int h = 0; h < 32; ++h) na += sT[warp][h] * sW2[h * 33 + lane];
        __syncwarp();
        sT[warp][lane] = na;
        __syncwarp();

        // ---- u[lane] = sum_h W2[lane][h] * node_att[h] ----
        float u = 0.f;
        #pragma unroll
        for (int h = 0; h < 32; ++h) u += sW2[lane * 33 + h] * sT[warp][h];
        __syncwarp();
        sT[warp][lane] = u;      // sT now holds u[h]
        __syncwarp();

        // ---- lane role for the main loop ----
        const int c  = lane & 7;    // h base: handles h = c, c+8, c+16, c+24
        const int gr = lane >> 3;   // row group: rows gr and gr+4 of each batch
        const float u0 = sT[warp][c];
        const float u1 = sT[warp][c + 8];
        const float u2 = sT[warp][c + 16];
        const float u3 = sT[warp][c + 24];

        const float4* rowW = &sRow[warp][0];

        float m = -1e30f, Z = 0.f;
        float4 agg = make_float4(0.f, 0.f, 0.f, 0.f);

        #pragma unroll 1
        for (int b = 0; b < NBATCH; ++b) {
            // stage RB rows, padded stride
            #pragma unroll
            for (int j = 0; j < RB; ++j)
                sRow[warp][j * RSTRIDE + lane] = nb4[(size_t)(b * RB + j) * 32 + lane];
            __syncwarp();

            u64 a0a = 0ull, a0b = 0ull, a1a = 0ull, a1b = 0ull;

            #pragma unroll
            for (int q = 0; q < 32; ++q) {
                float4 rA = rowW[gr * RSTRIDE + q];          // 4 distinct 16B: 1 wf
                float4 rB = rowW[(gr + 4) * RSTRIDE + q];    // 1 wf
                const ulonglong2* wq = &g_W2q[q * 32];
                #pragma unroll
                for (int i = 0; i < 4; ++i) {
                    ulonglong2 w = wq[i * 8 + c];            // 8 distinct in 1 line
                    float fA = fc(rA, i), fB = fc(rB, i);
                    u64 rA2 = pack2(fA, fA);
                    u64 rB2 = pack2(fB, fB);
                    a0a = ffma2(rA2, w.x, a0a);
                    a0b = ffma2(rA2, w.y, a0b);
                    a1a = ffma2(rB2, w.x, a1a);
                    a1b = ffma2(rB2, w.y, a1b);
                }
            }

            // tanh + dot with u over this lane's 4 h-columns
            float2 q0a = unpack2(a0a), q0b = unpack2(a0b);
            float2 q1a = unpack2(a1a), q1b = unpack2(a1b);
            float p0 = tanhf(q0a.x) * u0 + tanhf(q0a.y) * u1
                     + tanhf(q0b.x) * u2 + tanhf(q0b.y) * u3;
            float p1 = tanhf(q1a.x) * u0 + tanhf(q1a.y) * u1
                     + tanhf(q1b.x) * u2 + tanhf(q1b.y) * u3;

            // reduce within 8-lane group
            #pragma unroll
            for (int o = 1; o < 8; o <<= 1) {
                p0 += __shfl_xor_sync(0xffffffffu, p0, o);
                p1 += __shfl_xor_sync(0xffffffffu, p1, o);
            }
            // gather all 8 scores to every lane
            float s[RB];
            #pragma unroll
            for (int g = 0; g < 4; ++g) {
                s[g]     = __shfl_sync(0xffffffffu, p0, g * 8);
                s[g + 4] = __shfl_sync(0xffffffffu, p1, g * 8);
            }

            float bm = s[0];
            #pragma unroll
            for (int j = 1; j < RB; ++j) bm = fmaxf(bm, s[j]);
            float mn = fmaxf(m, bm);
            float corr = __expf(m - mn);
            Z *= corr;
            agg.x *= corr; agg.y *= corr; agg.z *= corr; agg.w *= corr;
            m = mn;
            #pragma unroll
            for (int j = 0; j < RB; ++j) {
                float e = __expf(s[j] - mn);
                Z += e;
                float4 v = rowW[j * RSTRIDE + lane];   // lane-indexed LDS.128
                agg.x += e * v.x; agg.y += e * v.y;
                agg.z += e * v.z; agg.w += e * v.w;
            }
            __syncwarp();
        }
        {
            float iz = 1.0f / Z;
            agg.x *= iz; agg.y *= iz; agg.z *= iz; agg.w *= iz;
        }
        sAgg[warp][lane] = agg;
    }

    // ================= block-cooperative epilogue =================
    // Thread t owns one output column for ALL 8 nodes of the block.
    __syncthreads();

    const bool useAgg = (tid >= 128);                    // warp-uniform
    const int  col    = tid & 127;
    const float* __restrict__ Wsel = useAgg ? W_neib : W_node;
    const float4 (*src)[32] = useAgg ? sAgg : sX;

    u64 acc2[4] = {0ull, 0ull, 0ull, 0ull};              // node pairs

    #pragma unroll 2
    for (int q = 0; q < 32; ++q) {
        float4 sv[8];
        #pragma unroll
        for (int w = 0; w < 8; ++w) sv[w] = src[w][q];   // broadcast LDS.128
        #pragma unroll
        for (int i = 0; i < 4; ++i) {
            float wv = Wsel[(size_t)(4 * q + i) * O + col];  // coalesced LDG.32
            u64 wv2 = pack2(wv, wv);
            acc2[0] = ffma2(pack2(fc(sv[0], i), fc(sv[1], i)), wv2, acc2[0]);
            acc2[1] = ffma2(pack2(fc(sv[2], i), fc(sv[3], i)), wv2, acc2[1]);
            acc2[2] = ffma2(pack2(fc(sv[4], i), fc(sv[5], i)), wv2, acc2[2]);
            acc2[3] = ffma2(pack2(fc(sv[6], i), fc(sv[7], i)), wv2, acc2[3]);
        }
    }

    const int base = blockIdx.x * WARPS;
    const int oc   = col + (useAgg ? O : 0);
    #pragma unroll
    for (int p = 0; p < 4; ++p) {
        float2 f = unpack2(acc2[p]);
        int n0 = base + 2 * p, n1 = n0 + 1;
        if (n0 < n) out[(size_t)n0 * (2 * O) + oc] = fmaxf(f.x, 0.f);
        if (n1 < n) out[(size_t)n1 * (2 * O) + oc] = fmaxf(f.y, 0.f);
    }
}

extern "C" void kernel_launch(void* const* d_in, const int* in_sizes, int n_in,
                              void* d_out, int out_size) {
    const float* node_feats = (const float*)d_in[0];
    const float* neib_feats = (const float*)d_in[1];
    // d_in[2] = node_ids, d_in[3] = neib_ids : unused by the reference computation
    const float* W_att1 = (const float*)d_in[4];
    const float* W_att2 = (const float*)d_in[5];
    const float* W_node = (const float*)d_in[6];
    const float* W_neib = (const float*)d_in[7];

    int n = in_sizes[0] / D;
    repack_w1_kernel<<<1, 1024>>>(W_att1);
    int blocks = (n + WARPS - 1) / WARPS;
    attn_agg_kernel<<<blocks, NTHREADS>>>(node_feats, neib_feats,
                                          W_att2, W_node, W_neib,
                                          (float*)d_out, n);
}

// round 8
// speedup vs baseline: 2.4834x; 1.1927x over previous
#include <cuda_runtime.h>

typedef unsigned long long u64;

constexpr int D = 128;   // feature dim
constexpr int K = 32;    // neighbors per node
constexpr int H = 32;    // attention hidden
constexpr int O = 128;   // output dim per branch
constexpr int WARPS = 8;            // nodes per block (1 warp per node)
constexpr int NTHREADS = WARPS * 32;
constexpr int RB = 16;              // neighbor rows per batch
constexpr int NBATCH = K / RB;      // 2
constexpr int RSTRIDE = 33;         // float4 units per staged row (528B, bank-pad)

// W1 packed for node-att phase: g_W1q[q*32+h] = d-quad (4q..4q+3) of column h.
__device__ ulonglong2 g_W1q[32 * 32];
// W1 packed for main loop: g_W2q[q*32 + i*8 + c] =
//   { pack2(W1[4q+i][c], W1[4q+i][c+8]), pack2(W1[4q+i][c+16], W1[4q+i][c+24]) }
__device__ ulonglong2 g_W2q[32 * 32];
// Output weights repacked: g_Wn4[q*128+col] = float4(W[4q..4q+3][col])
__device__ float4 g_Wn4[32 * 128];
__device__ float4 g_Wb4[32 * 128];

__device__ __forceinline__ u64 pack2(float lo, float hi) {
    u64 r; asm("mov.b64 %0, {%1, %2};" : "=l"(r) : "f"(lo), "f"(hi)); return r;
}
__device__ __forceinline__ float2 unpack2(u64 v) {
    float2 f; asm("mov.b64 {%0, %1}, %2;" : "=f"(f.x), "=f"(f.y) : "l"(v)); return f;
}
__device__ __forceinline__ u64 ffma2(u64 a, u64 b, u64 c) {
    u64 d; asm("fma.rn.f32x2 %0, %1, %2, %3;" : "=l"(d) : "l"(a), "l"(b), "l"(c)); return d;
}
__device__ __forceinline__ float fc(const float4& v, int i) {
    return i == 0 ? v.x : (i == 1 ? v.y : (i == 2 ? v.z : v.w));
}

__global__ void repack_kernel(const float* __restrict__ W_att1,
                              const float* __restrict__ W_node,
                              const float* __restrict__ W_neib) {
    int t = threadIdx.x;             // 1024 threads, one block
    if (t < 32 * 32) {
        int q = t >> 5, h = t & 31;
        ulonglong2 w;
        w.x = pack2(W_att1[(4 * q) * H + h],     W_att1[(4 * q + 1) * H + h]);
        w.y = pack2(W_att1[(4 * q + 2) * H + h], W_att1[(4 * q + 3) * H + h]);
        g_W1q[t] = w;
        int ii = h >> 3, c = h & 7;
        int d = 4 * q + ii;
        ulonglong2 w2;
        w2.x = pack2(W_att1[d * H + c],      W_att1[d * H + c + 8]);
        w2.y = pack2(W_att1[d * H + c + 16], W_att1[d * H + c + 24]);
        g_W2q[q * 32 + ii * 8 + c] = w2;
    }
    // repack output weights: 4096 entries each
    for (int i = t; i < 32 * 128; i += 1024) {
        int q = i >> 7, col = i & 127;
        g_Wn4[i] = make_float4(W_node[(4 * q) * O + col],     W_node[(4 * q + 1) * O + col],
                               W_node[(4 * q + 2) * O + col], W_node[(4 * q + 3) * O + col]);
        g_Wb4[i] = make_float4(W_neib[(4 * q) * O + col],     W_neib[(4 * q + 1) * O + col],
                               W_neib[(4 * q + 2) * O + col], W_neib[(4 * q + 3) * O + col]);
    }
}

// dynamic smem layout (bytes):
//   sRow : WARPS * RB * RSTRIDE float4          = 67584
//   sX   : WARPS * 32 float4                    = 4096
//   sAgg : WARPS * 32 float4                    = 4096
//   sW1s : 1024 ulonglong2                      = 16384
//   sW2  : 32*33 float                          = 4224
//   sT   : WARPS*32 float                       = 1024
constexpr int SM_ROW  = 0;
constexpr int SM_X    = SM_ROW + WARPS * RB * RSTRIDE * 16;
constexpr int SM_AGG  = SM_X + WARPS * 32 * 16;
constexpr int SM_W1   = SM_AGG + WARPS * 32 * 16;
constexpr int SM_W2   = SM_W1 + 1024 * 16;
constexpr int SM_T    = SM_W2 + 32 * 33 * 4;
constexpr int SMEM_BYTES = SM_T + WARPS * 32 * 4;   // 97408

__global__ __launch_bounds__(NTHREADS, 2)
void attn_agg_kernel(const float* __restrict__ node_feats,
                     const float* __restrict__ neib_feats,
                     const float* __restrict__ W_att2,   // [H,H] row-major
                     float* __restrict__ out,            // [N, 2*O]
                     int n)
{
    extern __shared__ char dsm[];
    float4*     sRowAll = reinterpret_cast<float4*>(dsm + SM_ROW);
    float4*     sX      = reinterpret_cast<float4*>(dsm + SM_X);
    float4*     sAgg    = reinterpret_cast<float4*>(dsm + SM_AGG);
    ulonglong2* sW1s    = reinterpret_cast<ulonglong2*>(dsm + SM_W1);
    float*      sW2     = reinterpret_cast<float*>(dsm + SM_W2);
    float*      sT      = reinterpret_cast<float*>(dsm + SM_T);

    const int tid  = threadIdx.x;
    const int lane = tid & 31;
    const int warp = tid >> 5;

    // stage W1 (main-loop layout) and W2 into smem once per block
    #pragma unroll
    for (int i = 0; i < 4; ++i) sW1s[tid + i * NTHREADS] = g_W2q[tid + i * NTHREADS];
    for (int i = tid; i < 32 * 32; i += NTHREADS)
        sW2[(i >> 5) * 33 + (i & 31)] = W_att2[i];
    __syncthreads();

    const int node = blockIdx.x * WARPS + warp;

    if (node < n) {
        const float* nrow = node_feats + (size_t)node * D;
        const float4* nb4 = reinterpret_cast<const float4*>(
                                neib_feats + (size_t)node * (K * D));
        float4* rowW = sRowAll + warp * (RB * RSTRIDE);

        // ---- stage node row ----
        sX[warp * 32 + lane] = reinterpret_cast<const float4*>(nrow)[lane];
        __syncwarp();

        // ---- t_node[lane] = tanh(node_row . W1[:,lane]) ----
        u64 a = 0ull;
        #pragma unroll
        for (int q = 0; q < 32; ++q) {
            ulonglong2 w = g_W1q[q * 32 + lane];
            float4 xv = sX[warp * 32 + q];
            a = ffma2(pack2(xv.x, xv.y), w.x, a);
            a = ffma2(pack2(xv.z, xv.w), w.y, a);
        }
        {
            float2 qa = unpack2(a);
            sT[warp * 32 + lane] = tanhf(qa.x + qa.y);
        }
        __syncwarp();

        // ---- node_att[lane] = sum_h t[h] * W2[h][lane] ----
        float na = 0.f;
        #pragma unroll
        for (int h = 0; h < 32; ++h) na += sT[warp * 32 + h] * sW2[h * 33 + lane];
        __syncwarp();
        sT[warp * 32 + lane] = na;
        __syncwarp();

        // ---- u[lane] = sum_h W2[lane][h] * node_att[h] ----
        float u = 0.f;
        #pragma unroll
        for (int h = 0; h < 32; ++h) u += sW2[lane * 33 + h] * sT[warp * 32 + h];
        __syncwarp();
        sT[warp * 32 + lane] = u;      // sT now holds u[h]
        __syncwarp();

        // ---- lane role ----
        const int c  = lane & 7;    // h columns: c, c+8, c+16, c+24
        const int gr = lane >> 3;   // rows: gr, gr+4, gr+8, gr+12
        const float u0 = sT[warp * 32 + c];
        const float u1 = sT[warp * 32 + c + 8];
        const float u2 = sT[warp * 32 + c + 16];
        const float u3 = sT[warp * 32 + c + 24];

        float m = -1e30f, Z = 0.f;
        float4 agg = make_float4(0.f, 0.f, 0.f, 0.f);

        #pragma unroll 1
        for (int b = 0; b < NBATCH; ++b) {
            // stage RB=16 rows, padded stride
            #pragma unroll
            for (int j = 0; j < RB; ++j)
                rowW[j * RSTRIDE + lane] = nb4[(size_t)(b * RB + j) * 32 + lane];
            __syncwarp();

            u64 accA[4], accB[4];
            #pragma unroll
            for (int j = 0; j < 4; ++j) { accA[j] = 0ull; accB[j] = 0ull; }

            #pragma unroll
            for (int q = 0; q < 32; ++q) {
                float4 r0 = rowW[(gr)      * RSTRIDE + q];   // rows: deduped LDS.128
                float4 r1 = rowW[(gr + 4)  * RSTRIDE + q];
                float4 r2 = rowW[(gr + 8)  * RSTRIDE + q];
                float4 r3 = rowW[(gr + 12) * RSTRIDE + q];
                const ulonglong2* wq = sW1s + q * 32;
                #pragma unroll
                for (int i = 0; i < 4; ++i) {
                    ulonglong2 w = wq[i * 8 + c];            // deduped LDS.128
                    float f0 = fc(r0, i), f1 = fc(r1, i), f2 = fc(r2, i), f3 = fc(r3, i);
                    u64 p0 = pack2(f0, f0), p1 = pack2(f1, f1);
                    u64 p2 = pack2(f2, f2), p3 = pack2(f3, f3);
                    accA[0] = ffma2(p0, w.x, accA[0]);  accB[0] = ffma2(p0, w.y, accB[0]);
                    accA[1] = ffma2(p1, w.x, accA[1]);  accB[1] = ffma2(p1, w.y, accB[1]);
                    accA[2] = ffma2(p2, w.x, accA[2]);  accB[2] = ffma2(p2, w.y, accB[2]);
                    accA[3] = ffma2(p3, w.x, accA[3]);  accB[3] = ffma2(p3, w.y, accB[3]);
                }
            }

            // tanh + dot with u over this lane's 4 h-columns; reduce per group
            float p[4];
            #pragma unroll
            for (int j = 0; j < 4; ++j) {
                float2 qa = unpack2(accA[j]), qb = unpack2(accB[j]);
                p[j] = tanhf(qa.x) * u0 + tanhf(qa.y) * u1
                     + tanhf(qb.x) * u2 + tanhf(qb.y) * u3;
                #pragma unroll
                for (int o = 1; o < 8; o <<= 1)
                    p[j] += __shfl_xor_sync(0xffffffffu, p[j], o);
            }
            // gather the 16 scores (row r = g + 4j held by lane g*8 reg p[j])
            float s[RB];
            #pragma unroll
            for (int r = 0; r < RB; ++r)
                s[r] = __shfl_sync(0xffffffffu, p[r >> 2], (r & 3) * 8);

            float bm = s[0];
            #pragma unroll
            for (int j = 1; j < RB; ++j) bm = fmaxf(bm, s[j]);
            float mn = fmaxf(m, bm);
            float corr = __expf(m - mn);
            Z *= corr;
            agg.x *= corr; agg.y *= corr; agg.z *= corr; agg.w *= corr;
            m = mn;
            #pragma unroll
            for (int j = 0; j < RB; ++j) {
                float e = __expf(s[j] - mn);
                Z += e;
                float4 v = rowW[j * RSTRIDE + lane];   // lane-indexed LDS.128
                agg.x += e * v.x; agg.y += e * v.y;
                agg.z += e * v.z; agg.w += e * v.w;
            }
            __syncwarp();
        }
        {
            float iz = 1.0f / Z;
            agg.x *= iz; agg.y *= iz; agg.z *= iz; agg.w *= iz;
        }
        sAgg[warp * 32 + lane] = agg;
    }

    // ================= block-cooperative epilogue =================
    // Thread t owns one output column for ALL 8 nodes of the block.
    __syncthreads();

    const bool useAgg = (tid >= 128);                    // warp-uniform
    const int  col    = tid & 127;
    const float4* __restrict__ W4 = useAgg ? g_Wb4 : g_Wn4;
    const float4* src = useAgg ? sAgg : sX;

    u64 acc2[4] = {0ull, 0ull, 0ull, 0ull};              // node pairs

    #pragma unroll 2
    for (int q = 0; q < 32; ++q) {
        float4 sv[8];
        #pragma unroll
        for (int w = 0; w < 8; ++w) sv[w] = src[w * 32 + q];  // broadcast LDS.128
        float4 wv = W4[q * 128 + col];                        // one coalesced LDG.128
        #pragma unroll
        for (int i = 0; i < 4; ++i) {
            float wf = fc(wv, i);
            u64 wv2 = pack2(wf, wf);
            acc2[0] = ffma2(pack2(fc(sv[0], i), fc(sv[1], i)), wv2, acc2[0]);
            acc2[1] = ffma2(pack2(fc(sv[2], i), fc(sv[3], i)), wv2, acc2[1]);
            acc2[2] = ffma2(pack2(fc(sv[4], i), fc(sv[5], i)), wv2, acc2[2]);
            acc2[3] = ffma2(pack2(fc(sv[6], i), fc(sv[7], i)), wv2, acc2[3]);
        }
    }

    const int base = blockIdx.x * WARPS;
    const int oc   = col + (useAgg ? O : 0);
    #pragma unroll
    for (int p = 0; p < 4; ++p) {
        float2 f = unpack2(acc2[p]);
        int n0 = base + 2 * p, n1 = n0 + 1;
        if (n0 < n) out[(size_t)n0 * (2 * O) + oc] = fmaxf(f.x, 0.f);
        if (n1 < n) out[(size_t)n1 * (2 * O) + oc] = fmaxf(f.y, 0.f);
    }
}

extern "C" void kernel_launch(void* const* d_in, const int* in_sizes, int n_in,
                              void* d_out, int out_size) {
    const float* node_feats = (const float*)d_in[0];
    const float* neib_feats = (const float*)d_in[1];
    // d_in[2] = node_ids, d_in[3] = neib_ids : unused by the reference computation
    const float* W_att1 = (const float*)d_in[4];
    const float* W_att2 = (const float*)d_in[5];
    const float* W_node = (const float*)d_in[6];
    const float* W_neib = (const float*)d_in[7];

    cudaFuncSetAttribute(attn_agg_kernel,
                         cudaFuncAttributeMaxDynamicSharedMemorySize, SMEM_BYTES);

    int n = in_sizes[0] / D;
    repack_kernel<<<1, 1024>>>(W_att1, W_node, W_neib);
    int blocks = (n + WARPS - 1) / WARPS;
    attn_agg_kernel<<<blocks, NTHREADS, SMEM_BYTES>>>(node_feats, neib_feats,
                                                      W_att2, (float*)d_out, n);
}